// round 3
// baseline (speedup 1.0000x reference)
#include <cuda_runtime.h>
#include <cuda_bf16.h>
#include <cstdint>

#define T_DIM   2048
#define B_DIM   128
#define IN_DIM  64
#define H_DIM   128
#define G_DIM   512
#define OUT_DIM 32
#define M_TOT   (T_DIM * B_DIM)   // 262144

// scratch (device globals: allocation-free per harness rules)
__device__ float g_xp[(size_t)M_TOT * G_DIM];  // 512 MB, reused by both layers
__device__ float g_y [(size_t)M_TOT * H_DIM];  // 128 MB, layer outputs (y0 then y1)

// ---------------- activations: single-MUFU tanh.approx ----------------------
__device__ __forceinline__ float tanh_f(float x) {
    float y; asm("tanh.approx.f32 %0, %1;" : "=f"(y) : "f"(x)); return y;
}
__device__ __forceinline__ float sigmoid_f(float x) {
    return 0.5f * tanh_f(0.5f * x) + 0.5f;
}

// ---------------- fp32 FFMA GEMM: C[m][g] = sum_k A[m][k]*W[g][k] -----------
// A: [M,K] row-major, W: [512,K] row-major. Tile 128x64, kc=16, 256 threads.
template<int K>
__global__ void __launch_bounds__(256) gemm_ih(const float* __restrict__ A,
                                               const float* __restrict__ W,
                                               float* __restrict__ C)
{
    __shared__ float As[16][132];   // pad 4: keeps 16B alignment, reduces store conflicts
    __shared__ float Ws[16][68];
    const int tid = threadIdx.x;
    const int m0 = blockIdx.y * 128, n0 = blockIdx.x * 64;
    const int tm = tid >> 4, tn = tid & 15;   // 16 x 16 thread grid
    float acc[8][4] = {};

    for (int k0 = 0; k0 < K; k0 += 16) {
        #pragma unroll
        for (int u = 0; u < 2; u++) {
            int idx = tid + u * 256;          // 0..511 -> 128 rows x 4 float4
            int row = idx >> 2, kq = idx & 3;
            float4 v = *reinterpret_cast<const float4*>(A + (size_t)(m0 + row) * K + k0 + kq * 4);
            As[kq * 4 + 0][row] = v.x; As[kq * 4 + 1][row] = v.y;
            As[kq * 4 + 2][row] = v.z; As[kq * 4 + 3][row] = v.w;
        }
        {
            int row = tid >> 2, kq = tid & 3; // 64 rows x 4 float4
            float4 v = *reinterpret_cast<const float4*>(W + (size_t)(n0 + row) * K + k0 + kq * 4);
            Ws[kq * 4 + 0][row] = v.x; Ws[kq * 4 + 1][row] = v.y;
            Ws[kq * 4 + 2][row] = v.z; Ws[kq * 4 + 3][row] = v.w;
        }
        __syncthreads();
        #pragma unroll
        for (int k = 0; k < 16; k++) {
            float a[8], b[4];
            #pragma unroll
            for (int i = 0; i < 8; i++) a[i] = As[k][tm * 8 + i];
            #pragma unroll
            for (int j = 0; j < 4; j++) b[j] = Ws[k][tn * 4 + j];
            #pragma unroll
            for (int i = 0; i < 8; i++)
                #pragma unroll
                for (int j = 0; j < 4; j++) acc[i][j] += a[i] * b[j];
        }
        __syncthreads();
    }
    #pragma unroll
    for (int i = 0; i < 8; i++) {
        float4 v = make_float4(acc[i][0], acc[i][1], acc[i][2], acc[i][3]);
        *reinterpret_cast<float4*>(C + (size_t)(m0 + tm * 8 + i) * G_DIM + n0 + tn * 4) = v;
    }
}

// ---------------- persistent per-batch LSTM recurrence ----------------------
// grid = 128 (one CTA per batch element), 512 threads (thread j = gate row).
// w_hh[j][0:64] in registers, w_hh[j][64:128] in smem ws[k][j].
// dyn smem: ws 64*512 f32 | h_s 128 | gate 512  = 133,632 B
#define REC_SMEM ((64 * 512 + 128 + 512) * 4)

__global__ void __launch_bounds__(512, 1) lstm_rec(const float* __restrict__ xp,
                                                   const float* __restrict__ whh,
                                                   float* __restrict__ y,
                                                   float* __restrict__ hn,
                                                   float* __restrict__ cn)
{
    extern __shared__ float sm[];
    float* ws   = sm;                 // [64][512]
    float* h_s  = sm + 64 * 512;      // [128]
    float* gate = h_s + 128;          // [512]

    const int b = blockIdx.x;
    const int j = threadIdx.x;

    float wr[64];
    #pragma unroll
    for (int k = 0; k < 64; k++) wr[k] = whh[j * H_DIM + k];
    #pragma unroll
    for (int k = 0; k < 64; k++) ws[k * 512 + j] = whh[j * H_DIM + 64 + k];
    if (j < H_DIM) h_s[j] = 0.0f;
    float c = 0.0f;
    __syncthreads();

    const float* xpb = xp + (size_t)b * G_DIM + j;
    float xv = xpb[0];

    for (int t = 0; t < T_DIM; t++) {
        float acc = xv;
        // prefetch next step's xp early; latency hidden by the dot product
        float xn = 0.0f;
        if (t + 1 < T_DIM) xn = xpb[(size_t)(t + 1) * B_DIM * G_DIM];

        #pragma unroll
        for (int k = 0; k < 64; k++) acc += wr[k] * h_s[k];
        #pragma unroll
        for (int k = 0; k < 64; k++) acc += ws[k * 512 + j] * h_s[64 + k];

        gate[j] = acc;
        __syncthreads();
        if (j < H_DIM) {
            float ig = sigmoid_f(gate[j]);
            float fg = sigmoid_f(gate[H_DIM + j]);
            float gg = tanh_f   (gate[2 * H_DIM + j]);
            float og = sigmoid_f(gate[3 * H_DIM + j]);
            c = fg * c + ig * gg;
            float h = og * tanh_f(c);
            h_s[j] = h;
            y[((size_t)t * B_DIM + b) * H_DIM + j] = h;
        }
        __syncthreads();
        xv = xn;
    }
    if (j < H_DIM) {
        hn[b * H_DIM + j] = h_s[j];
        cn[b * H_DIM + j] = c;
    }
}

// ---------------- FC head: out[m][o] = sum_k y[m][k]*fc_w[o][k] + b[o] ------
__global__ void __launch_bounds__(256) fc_head(const float* __restrict__ A,
                                               const float* __restrict__ W,
                                               const float* __restrict__ bias,
                                               float* __restrict__ C)
{
    __shared__ float ys[32][128];
    __shared__ float wst[128][32];
    const int tid = threadIdx.x;
    const int m0 = blockIdx.x * 32;

    for (int i = tid; i < OUT_DIM * H_DIM; i += 256) {
        int o = i / H_DIM, k = i % H_DIM;
        wst[k][o] = W[i];
    }
    for (int i = tid; i < 32 * H_DIM; i += 256) {
        int r = i / H_DIM, k = i % H_DIM;
        ys[r][k] = A[(size_t)(m0 + r) * H_DIM + k];
    }
    __syncthreads();

    const int o = tid & 31, mq = tid >> 5;    // mq: 0..7, each handles 4 rows
    float a0 = 0.f, a1 = 0.f, a2 = 0.f, a3 = 0.f;
    #pragma unroll 8
    for (int k = 0; k < H_DIM; k++) {
        float w = wst[k][o];
        a0 += ys[mq * 4 + 0][k] * w;
        a1 += ys[mq * 4 + 1][k] * w;
        a2 += ys[mq * 4 + 2][k] * w;
        a3 += ys[mq * 4 + 3][k] * w;
    }
    float bb = bias[o];
    C[(size_t)(m0 + mq * 4 + 0) * OUT_DIM + o] = a0 + bb;
    C[(size_t)(m0 + mq * 4 + 1) * OUT_DIM + o] = a1 + bb;
    C[(size_t)(m0 + mq * 4 + 2) * OUT_DIM + o] = a2 + bb;
    C[(size_t)(m0 + mq * 4 + 3) * OUT_DIM + o] = a3 + bb;
}

extern "C" void kernel_launch(void* const* d_in, const int* in_sizes, int n_in,
                              void* d_out, int out_size)
{
    const float* x     = (const float*)d_in[0];
    const float* w_ih0 = (const float*)d_in[1];
    const float* w_hh0 = (const float*)d_in[2];
    const float* w_ih1 = (const float*)d_in[3];
    const float* w_hh1 = (const float*)d_in[4];
    const float* fc_w  = (const float*)d_in[5];
    const float* fc_b  = (const float*)d_in[6];
    float* out = (float*)d_out;

    float* xp; cudaGetSymbolAddress((void**)&xp, g_xp);
    float* y;  cudaGetSymbolAddress((void**)&y,  g_y);

    float* hn = out + (size_t)M_TOT * OUT_DIM;            // [2,128,128]
    float* cn = hn + 2 * B_DIM * H_DIM;                   // [2,128,128]

    static bool attr_done = false;
    if (!attr_done) {
        cudaFuncSetAttribute(lstm_rec, cudaFuncAttributeMaxDynamicSharedMemorySize, REC_SMEM);
        attr_done = true;
    }

    dim3 gg0(G_DIM / 64, M_TOT / 128);
    // layer 0
    gemm_ih<IN_DIM><<<gg0, 256>>>(x, w_ih0, xp);
    lstm_rec<<<B_DIM, 512, REC_SMEM>>>(xp, w_hh0, y, hn, cn);
    // layer 1
    gemm_ih<H_DIM><<<gg0, 256>>>(y, w_ih1, xp);
    lstm_rec<<<B_DIM, 512, REC_SMEM>>>(xp, w_hh1, y, hn + B_DIM * H_DIM, cn + B_DIM * H_DIM);
    // FC head
    fc_head<<<M_TOT / 32, 256>>>(y, fc_w, fc_b, out);
}